// round 11
// baseline (speedup 1.0000x reference)
#include <cuda_runtime.h>
#include <cuda_bf16.h>

#define MAX_NODES 2097152
__device__ float4 g_pred4[MAX_NODES];   // pre-scaled nodal displacements (x*uc, y*uc, th*tc, 0)
__device__ float4 g_Fint4[MAX_NODES];   // accumulated internal forces (w unused)
__device__ double g_sumR;
__device__ double g_sumF;
__device__ unsigned int g_ticket;

// Pass 1: pack+scale pred into float4 AND zero the accumulator.
// 64 nodes/warp: two 24-lane LDG.128 batches issued back-to-back (MLP=2),
// stride-3 smem transpose (conflict-free), float4 stores.
__global__ void __launch_bounds__(256) pack_kernel(
        const float4* __restrict__ pred4in,
        const float*  __restrict__ pred,
        const float*  __restrict__ u_c,
        const float*  __restrict__ th_c,
        int N) {
    __shared__ float sm[8][192];
    const float uc = __ldg(u_c);
    const float tc = __ldg(th_c);
    const float4 z = make_float4(0.f, 0.f, 0.f, 0.f);

    const int lane  = threadIdx.x & 31;
    const int wib   = threadIdx.x >> 5;
    const int gwarp = (blockIdx.x * blockDim.x + threadIdx.x) >> 5;
    const int base  = gwarp * 64;

    if (base + 64 <= N) {
        // 64 nodes = 192 floats = 48 float4, starting at float index 3*base
        const float4* src = pred4in + ((3 * base) >> 2);   // base%64==0 -> aligned
        float4 v0, v1;
        if (lane < 24) {
            v0 = __ldcs(&src[lane]);          // both in flight together
            v1 = __ldcs(&src[lane + 24]);
        }
        if (lane < 24) {
            ((float4*)sm[wib])[lane]      = v0;
            ((float4*)sm[wib])[lane + 24] = v1;
        }
        __syncwarp();
        const float x0 = sm[wib][3 * lane + 0];
        const float y0 = sm[wib][3 * lane + 1];
        const float t0 = sm[wib][3 * lane + 2];
        const float x1 = sm[wib][96 + 3 * lane + 0];
        const float y1 = sm[wib][96 + 3 * lane + 1];
        const float t1 = sm[wib][96 + 3 * lane + 2];
        g_pred4[base + lane]      = make_float4(x0 * uc, y0 * uc, t0 * tc, 0.f);
        g_pred4[base + 32 + lane] = make_float4(x1 * uc, y1 * uc, t1 * tc, 0.f);
        g_Fint4[base + lane]      = z;
        g_Fint4[base + 32 + lane] = z;
    } else {
        // tail warp: scalar path for the remaining (<64) nodes
        for (int i = base + lane; i < N; i += 32) {
            g_pred4[i] = make_float4(pred[3 * i] * uc, pred[3 * i + 1] * uc,
                                     pred[3 * i + 2] * tc, 0.f);
            g_Fint4[i] = z;
        }
    }
}

__device__ __forceinline__ void red_v4(float4* addr, float x, float y, float z, float w) {
    asm volatile("red.global.add.v4.f32 [%0], {%1, %2, %3, %4};"
                 :: "l"(addr), "f"(x), "f"(y), "f"(z), "f"(w) : "memory");
}

// Pass 2: per-element local forces, scatter-add via v4 REDG. 1 elem/thread.
// (Proven floor configuration — unchanged.)
__global__ void __launch_bounds__(256) elem_kernel(
        const float* __restrict__ L,
        const float* __restrict__ pE,
        const float* __restrict__ pA,
        const float* __restrict__ pI,
        const float* __restrict__ dirs,
        const int2*  __restrict__ conn,
        int E) {
    const int e = blockIdx.x * blockDim.x + threadIdx.x;
    if (e >= E) return;

    const int2 ab = __ldcs(&conn[e]);
    const float c  = __ldcs(&dirs[3 * e + 0]);
    const float s  = __ldcs(&dirs[3 * e + 2]);
    const float Le = __ldcs(&L[e]);
    const float Ee = __ldcs(&pE[e]);
    const float EA = Ee * __ldcs(&pA[e]);
    const float EI = Ee * __ldcs(&pI[e]);

    const float4 a = g_pred4[ab.x];
    const float4 b = g_pred4[ab.y];

    const float u_A  =  c * a.x + s * a.y;
    const float w_A  = -s * a.x + c * a.y;
    const float thA  = -a.z;
    const float u_B  =  c * b.x + s * b.y;
    const float w_B  = -s * b.x + c * b.y;
    const float thB  = -b.z;

    const float inv_L = 1.0f / Le;
    const float ea_l  = EA * inv_L;            // AXIAL_WEIGHT = 1
    const float ei_l  = EI * inv_L;
    const float ei_l2 = ei_l * inv_L;
    const float ei_l3 = ei_l2 * inv_L;

    const float dw = w_A - w_B;
    const float f0 = ea_l * (u_A - u_B);
    const float f1 = 12.0f * ei_l3 * dw + 6.0f * ei_l2 * (thA + thB);
    const float f2 = 6.0f * ei_l2 * dw + 4.0f * ei_l * thA + 2.0f * ei_l * thB;
    const float f5 = 6.0f * ei_l2 * dw + 2.0f * ei_l * thA + 4.0f * ei_l * thB;

    const float fAx = c * f0 - s * f1;
    const float fAy = s * f0 + c * f1;

    red_v4(&g_Fint4[ab.x],  fAx,  fAy, -f2, 0.0f);
    red_v4(&g_Fint4[ab.y], -fAx, -fAy, -f5, 0.0f);
}

// Pass 3: masked residual norm, fused finalize, self-resetting accumulators.
// (Unchanged.)
__global__ void node_kernel(const float* __restrict__ F_ext,
                            const float* __restrict__ bc_disp,
                            const float* __restrict__ bc_rot,
                            float* __restrict__ out,
                            int N) {
    int i = blockIdx.x * blockDim.x + threadIdx.x;
    const int stride = gridDim.x * blockDim.x;

    float lr = 0.0f;
    float lf = 0.0f;
    for (; i < N; i += stride) {
        const float md = 1.0f - __ldcs(&bc_disp[i]);
        const float mr = 1.0f - __ldcs(&bc_rot[i]);
        const float Fe0 = __ldcs(&F_ext[3 * i + 0]);
        const float Fe1 = __ldcs(&F_ext[3 * i + 1]);
        const float Fe2 = __ldcs(&F_ext[3 * i + 2]);
        const float4 Fi = __ldcs(&g_Fint4[i]);
        const float R0 = (Fi.x - Fe0) * md;
        const float R1 = (Fi.y - Fe1) * md;
        const float R2 = (Fi.z - Fe2) * mr;
        const float F0 = Fe0 * md;
        const float F1 = Fe1 * md;
        const float F2 = Fe2 * mr;
        lr += R0 * R0 + R1 * R1 + R2 * R2;
        lf += F0 * F0 + F1 * F1 + F2 * F2;
    }

    #pragma unroll
    for (int off = 16; off > 0; off >>= 1) {
        lr += __shfl_down_sync(0xFFFFFFFFu, lr, off);
        lf += __shfl_down_sync(0xFFFFFFFFu, lf, off);
    }

    __shared__ float s_r[32];
    __shared__ float s_f[32];
    const int lane = threadIdx.x & 31;
    const int wid  = threadIdx.x >> 5;
    if (lane == 0) { s_r[wid] = lr; s_f[wid] = lf; }
    __syncthreads();

    __shared__ bool s_last;
    if (wid == 0) {
        const int nwarps = (blockDim.x + 31) >> 5;
        lr = (lane < nwarps) ? s_r[lane] : 0.0f;
        lf = (lane < nwarps) ? s_f[lane] : 0.0f;
        #pragma unroll
        for (int off = 16; off > 0; off >>= 1) {
            lr += __shfl_down_sync(0xFFFFFFFFu, lr, off);
            lf += __shfl_down_sync(0xFFFFFFFFu, lf, off);
        }
        if (lane == 0) {
            atomicAdd(&g_sumR, (double)lr);
            atomicAdd(&g_sumF, (double)lf);
            __threadfence();
            unsigned int t = atomicAdd(&g_ticket, 1u);
            s_last = (t == (unsigned int)(gridDim.x - 1));
        }
    }
    __syncthreads();

    if (threadIdx.x == 0 && s_last) {
        double f = g_sumF;
        if (f < 1e-30) f = 1e-30;
        out[0] = (float)(g_sumR / f);
        g_sumR = 0.0;
        g_sumF = 0.0;
        __threadfence();
        g_ticket = 0u;
    }
}

extern "C" void kernel_launch(void* const* d_in, const int* in_sizes, int n_in,
                              void* d_out, int out_size) {
    const float* pred   = (const float*)d_in[0];
    const float* u_c    = (const float*)d_in[1];
    const float* th_c   = (const float*)d_in[2];
    const float* L      = (const float*)d_in[3];
    const float* pE     = (const float*)d_in[4];
    const float* pA     = (const float*)d_in[5];
    const float* pI     = (const float*)d_in[6];
    const float* dirs   = (const float*)d_in[7];
    const float* F_ext  = (const float*)d_in[8];
    const float* bcd    = (const float*)d_in[9];
    const float* bcr    = (const float*)d_in[10];
    const int*   conn   = (const int*)d_in[11];

    const int N = in_sizes[0] / 3;
    const int E = in_sizes[3];

    float* out = (float*)d_out;

    {
        // one 64-node group per warp (+1 tail warp)
        int warps = (N + 63) / 64 + 1;
        int threads = 256;
        int blocks = (warps + 7) / 8;
        pack_kernel<<<blocks, threads>>>((const float4*)pred, pred, u_c, th_c, N);
    }
    {
        int threads = 256;
        int blocks = (E + threads - 1) / threads;
        elem_kernel<<<blocks, threads>>>(L, pE, pA, pI, dirs, (const int2*)conn, E);
    }
    {
        int threads = 256;
        int blocks = (N + threads - 1) / threads;
        if (blocks > 2368) blocks = 2368;
        node_kernel<<<blocks, threads>>>(F_ext, bcd, bcr, out, N);
    }
}

// round 12
// speedup vs baseline: 1.0130x; 1.0130x over previous
#include <cuda_runtime.h>
#include <cuda_bf16.h>

#define MAX_NODES 2097152
__device__ float4 g_pred4[MAX_NODES];   // pre-scaled nodal displacements (x*uc, y*uc, th*tc, 0)
__device__ float4 g_Fint4[MAX_NODES];   // accumulated internal forces (w unused)
__device__ double g_sumR;
__device__ double g_sumF;
__device__ unsigned int g_ticket;

// Pass 1 (R10 best): pack+scale pred into float4 AND zero the accumulator.
// Warp-coalesced: 24 lanes LDG.128 the 96 floats for 32 nodes, transpose via
// smem (stride-3 LDS = conflict-free), 1 node/thread float4 stores.
__global__ void __launch_bounds__(256) pack_kernel(
        const float4* __restrict__ pred4in,
        const float*  __restrict__ pred,
        const float*  __restrict__ u_c,
        const float*  __restrict__ th_c,
        int N) {
    __shared__ float sm[8][96];
    const float uc = __ldg(u_c);
    const float tc = __ldg(th_c);
    const float4 z = make_float4(0.f, 0.f, 0.f, 0.f);

    const int lane = threadIdx.x & 31;
    const int wib  = threadIdx.x >> 5;                       // warp in block
    const int gwarp = (blockIdx.x * blockDim.x + threadIdx.x) >> 5;
    const int nwarps = (gridDim.x * blockDim.x) >> 5;

    for (int base = gwarp * 32; base < N; base += nwarps * 32) {
        if (base + 32 <= N) {
            // 32 nodes = 96 floats = 24 float4, starting at float index 3*base
            const float4* src = pred4in + (3 * base >> 2);   // base%32==0 -> aligned
            if (lane < 24) {
                ((float4*)sm[wib])[lane] = __ldcs(&src[lane]);
            }
            __syncwarp();
            const float x = sm[wib][3 * lane + 0];
            const float y = sm[wib][3 * lane + 1];
            const float t = sm[wib][3 * lane + 2];
            __syncwarp();
            g_pred4[base + lane] = make_float4(x * uc, y * uc, t * tc, 0.f);
            g_Fint4[base + lane] = z;
        } else {
            const int i = base + lane;
            if (i < N) {
                g_pred4[i] = make_float4(pred[3 * i] * uc, pred[3 * i + 1] * uc,
                                         pred[3 * i + 2] * tc, 0.f);
                g_Fint4[i] = z;
            }
        }
    }
}

__device__ __forceinline__ void red_v4(float4* addr, float x, float y, float z, float w) {
    asm volatile("red.global.add.v4.f32 [%0], {%1, %2, %3, %4};"
                 :: "l"(addr), "f"(x), "f"(y), "f"(z), "f"(w) : "memory");
}

// Pass 2: per-element local forces, scatter-add via v4 REDG. 1 elem/thread.
// (Proven floor configuration — unchanged.)
__global__ void __launch_bounds__(256) elem_kernel(
        const float* __restrict__ L,
        const float* __restrict__ pE,
        const float* __restrict__ pA,
        const float* __restrict__ pI,
        const float* __restrict__ dirs,
        const int2*  __restrict__ conn,
        int E) {
    const int e = blockIdx.x * blockDim.x + threadIdx.x;
    if (e >= E) return;

    const int2 ab = __ldcs(&conn[e]);
    const float c  = __ldcs(&dirs[3 * e + 0]);
    const float s  = __ldcs(&dirs[3 * e + 2]);
    const float Le = __ldcs(&L[e]);
    const float Ee = __ldcs(&pE[e]);
    const float EA = Ee * __ldcs(&pA[e]);
    const float EI = Ee * __ldcs(&pI[e]);

    const float4 a = g_pred4[ab.x];
    const float4 b = g_pred4[ab.y];

    const float u_A  =  c * a.x + s * a.y;
    const float w_A  = -s * a.x + c * a.y;
    const float thA  = -a.z;
    const float u_B  =  c * b.x + s * b.y;
    const float w_B  = -s * b.x + c * b.y;
    const float thB  = -b.z;

    const float inv_L = 1.0f / Le;
    const float ea_l  = EA * inv_L;            // AXIAL_WEIGHT = 1
    const float ei_l  = EI * inv_L;
    const float ei_l2 = ei_l * inv_L;
    const float ei_l3 = ei_l2 * inv_L;

    const float dw = w_A - w_B;
    const float f0 = ea_l * (u_A - u_B);
    const float f1 = 12.0f * ei_l3 * dw + 6.0f * ei_l2 * (thA + thB);
    const float f2 = 6.0f * ei_l2 * dw + 4.0f * ei_l * thA + 2.0f * ei_l * thB;
    const float f5 = 6.0f * ei_l2 * dw + 2.0f * ei_l * thA + 4.0f * ei_l * thB;

    const float fAx = c * f0 - s * f1;
    const float fAy = s * f0 + c * f1;

    red_v4(&g_Fint4[ab.x],  fAx,  fAy, -f2, 0.0f);
    red_v4(&g_Fint4[ab.y], -fAx, -fAy, -f5, 0.0f);
}

// Pass 3 (R8 node, measured ~1us faster): masked residual norm, 2 nodes/thread,
// fused finalize + self-reset.
__global__ void node_kernel(const float2* __restrict__ Fe2,
                            const float*  __restrict__ F_ext,
                            const float2* __restrict__ bcd2,
                            const float2* __restrict__ bcr2,
                            const float*  __restrict__ bcd,
                            const float*  __restrict__ bcr,
                            float* __restrict__ out,
                            int Ngrp, int N) {
    int g = blockIdx.x * blockDim.x + threadIdx.x;
    const int stride = gridDim.x * blockDim.x;

    float lr = 0.0f;
    float lf = 0.0f;
    for (; g < Ngrp; g += stride) {
        const float2 dd = __ldcs(&bcd2[g]);
        const float2 rr = __ldcs(&bcr2[g]);
        const float2 e0 = __ldcs(&Fe2[3 * g + 0]);   // (Fx0, Fy0)
        const float2 e1 = __ldcs(&Fe2[3 * g + 1]);   // (Ft0, Fx1)
        const float2 e2 = __ldcs(&Fe2[3 * g + 2]);   // (Fy1, Ft1)
        const int n = 2 * g;
        const float4 i0 = __ldcs(&g_Fint4[n + 0]);
        const float4 i1 = __ldcs(&g_Fint4[n + 1]);
        {
            const float md = 1.0f - dd.x, mr = 1.0f - rr.x;
            const float R0 = (i0.x - e0.x) * md;
            const float R1 = (i0.y - e0.y) * md;
            const float R2 = (i0.z - e1.x) * mr;
            const float F0 = e0.x * md, F1 = e0.y * md, F2 = e1.x * mr;
            lr += R0*R0 + R1*R1 + R2*R2;
            lf += F0*F0 + F1*F1 + F2*F2;
        }
        {
            const float md = 1.0f - dd.y, mr = 1.0f - rr.y;
            const float R0 = (i1.x - e1.y) * md;
            const float R1 = (i1.y - e2.x) * md;
            const float R2 = (i1.z - e2.y) * mr;
            const float F0 = e1.y * md, F1 = e2.x * md, F2 = e2.y * mr;
            lr += R0*R0 + R1*R1 + R2*R2;
            lf += F0*F0 + F1*F1 + F2*F2;
        }
    }
    // scalar tail (N odd)
    {
        const int i = 2 * Ngrp + (blockIdx.x * blockDim.x + threadIdx.x);
        if (i < N) {
            const float md = 1.0f - bcd[i];
            const float mr = 1.0f - bcr[i];
            const float Fe0 = F_ext[3 * i + 0];
            const float Fe1 = F_ext[3 * i + 1];
            const float Fe2v = F_ext[3 * i + 2];
            const float4 Fi = g_Fint4[i];
            const float R0 = (Fi.x - Fe0) * md;
            const float R1 = (Fi.y - Fe1) * md;
            const float R2 = (Fi.z - Fe2v) * mr;
            lr += R0*R0 + R1*R1 + R2*R2;
            lf += (Fe0*md)*(Fe0*md) + (Fe1*md)*(Fe1*md) + (Fe2v*mr)*(Fe2v*mr);
        }
    }

    #pragma unroll
    for (int off = 16; off > 0; off >>= 1) {
        lr += __shfl_down_sync(0xFFFFFFFFu, lr, off);
        lf += __shfl_down_sync(0xFFFFFFFFu, lf, off);
    }

    __shared__ float s_r[32];
    __shared__ float s_f[32];
    const int lane = threadIdx.x & 31;
    const int wid  = threadIdx.x >> 5;
    if (lane == 0) { s_r[wid] = lr; s_f[wid] = lf; }
    __syncthreads();

    __shared__ bool s_last;
    if (wid == 0) {
        const int nwarps = (blockDim.x + 31) >> 5;
        lr = (lane < nwarps) ? s_r[lane] : 0.0f;
        lf = (lane < nwarps) ? s_f[lane] : 0.0f;
        #pragma unroll
        for (int off = 16; off > 0; off >>= 1) {
            lr += __shfl_down_sync(0xFFFFFFFFu, lr, off);
            lf += __shfl_down_sync(0xFFFFFFFFu, lf, off);
        }
        if (lane == 0) {
            atomicAdd(&g_sumR, (double)lr);
            atomicAdd(&g_sumF, (double)lf);
            __threadfence();
            unsigned int t = atomicAdd(&g_ticket, 1u);
            s_last = (t == (unsigned int)(gridDim.x - 1));
        }
    }
    __syncthreads();

    if (threadIdx.x == 0 && s_last) {
        double f = g_sumF;
        if (f < 1e-30) f = 1e-30;
        out[0] = (float)(g_sumR / f);
        g_sumR = 0.0;
        g_sumF = 0.0;
        __threadfence();
        g_ticket = 0u;
    }
}

extern "C" void kernel_launch(void* const* d_in, const int* in_sizes, int n_in,
                              void* d_out, int out_size) {
    const float* pred   = (const float*)d_in[0];
    const float* u_c    = (const float*)d_in[1];
    const float* th_c   = (const float*)d_in[2];
    const float* L      = (const float*)d_in[3];
    const float* pE     = (const float*)d_in[4];
    const float* pA     = (const float*)d_in[5];
    const float* pI     = (const float*)d_in[6];
    const float* dirs   = (const float*)d_in[7];
    const float* F_ext  = (const float*)d_in[8];
    const float* bcd    = (const float*)d_in[9];
    const float* bcr    = (const float*)d_in[10];
    const int*   conn   = (const int*)d_in[11];

    const int N = in_sizes[0] / 3;
    const int E = in_sizes[3];

    float* out = (float*)d_out;

    {
        // one 32-node group per warp (R10 config)
        int threads = 256;
        int warps_needed = (N + 31) / 32;
        int blocks = (warps_needed + 7) / 8;     // 8 warps per block
        if (blocks > 4096) blocks = 4096;
        pack_kernel<<<blocks, threads>>>((const float4*)pred, pred, u_c, th_c, N);
    }
    {
        int threads = 256;
        int blocks = (E + threads - 1) / threads;
        elem_kernel<<<blocks, threads>>>(L, pE, pA, pI, dirs, (const int2*)conn, E);
    }
    {
        const int Ngrp = N / 2;
        int threads = 256;
        int blocks = (Ngrp + threads - 1) / threads;
        node_kernel<<<blocks, threads>>>((const float2*)F_ext, F_ext,
                                         (const float2*)bcd, (const float2*)bcr,
                                         bcd, bcr, out, Ngrp, N);
    }
}

// round 13
// speedup vs baseline: 1.0185x; 1.0054x over previous
#include <cuda_runtime.h>
#include <cuda_bf16.h>

#define MAX_NODES 2097152
__device__ float4 g_pred4[MAX_NODES];   // pre-scaled nodal displacements (x*uc, y*uc, th*tc, 0)
__device__ float4 g_Fint4[MAX_NODES];   // accumulated internal forces (w unused)
__device__ double g_sumR;
__device__ double g_sumF;
__device__ unsigned int g_ticket;

// Pass 1 (R10 best): pack+scale pred into float4 AND zero the accumulator.
// Warp-coalesced: 24 lanes LDG.128 the 96 floats for 32 nodes, stride-3 smem
// transpose (conflict-free), 1 node/thread float4 stores.
// Triggers PDL completion so elem can launch while pack drains.
__global__ void __launch_bounds__(256) pack_kernel(
        const float4* __restrict__ pred4in,
        const float*  __restrict__ pred,
        const float*  __restrict__ u_c,
        const float*  __restrict__ th_c,
        int N) {
    __shared__ float sm[8][96];
    const float uc = __ldg(u_c);
    const float tc = __ldg(th_c);
    const float4 z = make_float4(0.f, 0.f, 0.f, 0.f);

    const int lane = threadIdx.x & 31;
    const int wib  = threadIdx.x >> 5;                       // warp in block
    const int gwarp = (blockIdx.x * blockDim.x + threadIdx.x) >> 5;
    const int nwarps = (gridDim.x * blockDim.x) >> 5;

    for (int base = gwarp * 32; base < N; base += nwarps * 32) {
        if (base + 32 <= N) {
            const float4* src = pred4in + (3 * base >> 2);   // base%32==0 -> aligned
            if (lane < 24) {
                ((float4*)sm[wib])[lane] = __ldcs(&src[lane]);
            }
            __syncwarp();
            const float x = sm[wib][3 * lane + 0];
            const float y = sm[wib][3 * lane + 1];
            const float t = sm[wib][3 * lane + 2];
            __syncwarp();
            g_pred4[base + lane] = make_float4(x * uc, y * uc, t * tc, 0.f);
            g_Fint4[base + lane] = z;
        } else {
            const int i = base + lane;
            if (i < N) {
                g_pred4[i] = make_float4(pred[3 * i] * uc, pred[3 * i + 1] * uc,
                                         pred[3 * i + 2] * tc, 0.f);
                g_Fint4[i] = z;
            }
        }
    }
#if __CUDA_ARCH__ >= 900
    cudaTriggerProgrammaticLaunchCompletion();
#endif
}

__device__ __forceinline__ void red_v4(float4* addr, float x, float y, float z, float w) {
    asm volatile("red.global.add.v4.f32 [%0], {%1, %2, %3, %4];" ::: );
}
// (note: real definition below — placeholder removed)
#undef RED_V4_PLACEHOLDER

__device__ __forceinline__ void red_v4_(float4* addr, float x, float y, float z, float w) {
    asm volatile("red.global.add.v4.f32 [%0], {%1, %2, %3, %4};"
                 :: "l"(addr), "f"(x), "f"(y), "f"(z), "f"(w) : "memory");
}

// Pass 2: per-element local forces, scatter-add via v4 REDG. 1 elem/thread.
// PDL: streaming operands loaded BEFORE the grid-dependency sync; gathers and
// REDGs (which touch pack's output) after it.
__global__ void __launch_bounds__(256) elem_kernel(
        const float* __restrict__ L,
        const float* __restrict__ pE,
        const float* __restrict__ pA,
        const float* __restrict__ pI,
        const float* __restrict__ dirs,
        const int2*  __restrict__ conn,
        int E) {
    const int e = blockIdx.x * blockDim.x + threadIdx.x;

    int2 ab = make_int2(0, 0);
    float c = 0.f, s = 0.f, Le = 1.f, Ee = 0.f, Ae = 0.f, Ie = 0.f;
    if (e < E) {
        ab = __ldcs(&conn[e]);
        c  = __ldcs(&dirs[3 * e + 0]);
        s  = __ldcs(&dirs[3 * e + 2]);
        Le = __ldcs(&L[e]);
        Ee = __ldcs(&pE[e]);
        Ae = __ldcs(&pA[e]);
        Ie = __ldcs(&pI[e]);
    }

#if __CUDA_ARCH__ >= 900
    cudaGridDependencySynchronize();   // pack's stores now visible
#endif
    if (e >= E) return;

    const float EA = Ee * Ae;
    const float EI = Ee * Ie;

    const float4 a = g_pred4[ab.x];
    const float4 b = g_pred4[ab.y];

    const float u_A  =  c * a.x + s * a.y;
    const float w_A  = -s * a.x + c * a.y;
    const float thA  = -a.z;
    const float u_B  =  c * b.x + s * b.y;
    const float w_B  = -s * b.x + c * b.y;
    const float thB  = -b.z;

    const float inv_L = 1.0f / Le;
    const float ea_l  = EA * inv_L;            // AXIAL_WEIGHT = 1
    const float ei_l  = EI * inv_L;
    const float ei_l2 = ei_l * inv_L;
    const float ei_l3 = ei_l2 * inv_L;

    const float dw = w_A - w_B;
    const float f0 = ea_l * (u_A - u_B);
    const float f1 = 12.0f * ei_l3 * dw + 6.0f * ei_l2 * (thA + thB);
    const float f2 = 6.0f * ei_l2 * dw + 4.0f * ei_l * thA + 2.0f * ei_l * thB;
    const float f5 = 6.0f * ei_l2 * dw + 2.0f * ei_l * thA + 4.0f * ei_l * thB;

    const float fAx = c * f0 - s * f1;
    const float fAy = s * f0 + c * f1;

    red_v4_(&g_Fint4[ab.x],  fAx,  fAy, -f2, 0.0f);
    red_v4_(&g_Fint4[ab.y], -fAx, -fAy, -f5, 0.0f);
}

// Pass 3 (R10 scalar node): masked residual norm, fused finalize + self-reset.
// PDL: independent streams loaded before the sync; Fint read after.
__global__ void node_kernel(const float* __restrict__ F_ext,
                            const float* __restrict__ bc_disp,
                            const float* __restrict__ bc_rot,
                            float* __restrict__ out,
                            int N) {
    const int i0 = blockIdx.x * blockDim.x + threadIdx.x;
    const int stride = gridDim.x * blockDim.x;

    // Prefetch first iteration's independent streams before the dependency sync.
    float pmd = 0.f, pmr = 0.f, pe0 = 0.f, pe1 = 0.f, pe2 = 0.f;
    if (i0 < N) {
        pmd = __ldcs(&bc_disp[i0]);
        pmr = __ldcs(&bc_rot[i0]);
        pe0 = __ldcs(&F_ext[3 * i0 + 0]);
        pe1 = __ldcs(&F_ext[3 * i0 + 1]);
        pe2 = __ldcs(&F_ext[3 * i0 + 2]);
    }
#if __CUDA_ARCH__ >= 900
    cudaGridDependencySynchronize();   // elem's REDGs now visible
#endif

    float lr = 0.0f;
    float lf = 0.0f;
    bool first = true;
    for (int i = i0; i < N; i += stride) {
        float md, mr, Fe0, Fe1, Fe2;
        if (first) {
            md = 1.0f - pmd; mr = 1.0f - pmr;
            Fe0 = pe0; Fe1 = pe1; Fe2 = pe2;
            first = false;
        } else {
            md = 1.0f - __ldcs(&bc_disp[i]);
            mr = 1.0f - __ldcs(&bc_rot[i]);
            Fe0 = __ldcs(&F_ext[3 * i + 0]);
            Fe1 = __ldcs(&F_ext[3 * i + 1]);
            Fe2 = __ldcs(&F_ext[3 * i + 2]);
        }
        const float4 Fi = __ldcs(&g_Fint4[i]);
        const float R0 = (Fi.x - Fe0) * md;
        const float R1 = (Fi.y - Fe1) * md;
        const float R2 = (Fi.z - Fe2) * mr;
        const float F0 = Fe0 * md;
        const float F1 = Fe1 * md;
        const float F2 = Fe2 * mr;
        lr += R0 * R0 + R1 * R1 + R2 * R2;
        lf += F0 * F0 + F1 * F1 + F2 * F2;
    }

    #pragma unroll
    for (int off = 16; off > 0; off >>= 1) {
        lr += __shfl_down_sync(0xFFFFFFFFu, lr, off);
        lf += __shfl_down_sync(0xFFFFFFFFu, lf, off);
    }

    __shared__ float s_r[32];
    __shared__ float s_f[32];
    const int lane = threadIdx.x & 31;
    const int wid  = threadIdx.x >> 5;
    if (lane == 0) { s_r[wid] = lr; s_f[wid] = lf; }
    __syncthreads();

    __shared__ bool s_last;
    if (wid == 0) {
        const int nwarps = (blockDim.x + 31) >> 5;
        lr = (lane < nwarps) ? s_r[lane] : 0.0f;
        lf = (lane < nwarps) ? s_f[lane] : 0.0f;
        #pragma unroll
        for (int off = 16; off > 0; off >>= 1) {
            lr += __shfl_down_sync(0xFFFFFFFFu, lr, off);
            lf += __shfl_down_sync(0xFFFFFFFFu, lf, off);
        }
        if (lane == 0) {
            atomicAdd(&g_sumR, (double)lr);
            atomicAdd(&g_sumF, (double)lf);
            __threadfence();
            unsigned int t = atomicAdd(&g_ticket, 1u);
            s_last = (t == (unsigned int)(gridDim.x - 1));
        }
    }
    __syncthreads();

    if (threadIdx.x == 0 && s_last) {
        double f = g_sumF;
        if (f < 1e-30) f = 1e-30;
        out[0] = (float)(g_sumR / f);
        g_sumR = 0.0;
        g_sumF = 0.0;
        __threadfence();
        g_ticket = 0u;
    }
}

extern "C" void kernel_launch(void* const* d_in, const int* in_sizes, int n_in,
                              void* d_out, int out_size) {
    const float* pred   = (const float*)d_in[0];
    const float* u_c    = (const float*)d_in[1];
    const float* th_c   = (const float*)d_in[2];
    const float* L      = (const float*)d_in[3];
    const float* pE     = (const float*)d_in[4];
    const float* pA     = (const float*)d_in[5];
    const float* pI     = (const float*)d_in[6];
    const float* dirs   = (const float*)d_in[7];
    const float* F_ext  = (const float*)d_in[8];
    const float* bcd    = (const float*)d_in[9];
    const float* bcr    = (const float*)d_in[10];
    const int*   conn   = (const int*)d_in[11];

    const int N = in_sizes[0] / 3;
    const int E = in_sizes[3];

    float* out = (float*)d_out;

    // --- pack (R10 config) ---
    {
        int threads = 256;
        int warps_needed = (N + 31) / 32;
        int blocks = (warps_needed + 7) / 8;
        if (blocks > 4096) blocks = 4096;
        pack_kernel<<<blocks, threads>>>((const float4*)pred, pred, u_c, th_c, N);
    }

    cudaLaunchAttribute pdl[1];
    pdl[0].id = cudaLaunchAttributeProgrammaticStreamSerialization;
    pdl[0].val.programmaticStreamSerializationAllowed = 1;

    // --- elem (PDL: launches while pack drains) ---
    {
        cudaLaunchConfig_t cfg = {};
        cfg.gridDim  = dim3((E + 255) / 256);
        cfg.blockDim = dim3(256);
        cfg.stream   = 0;
        cfg.attrs    = pdl;
        cfg.numAttrs = 1;
        cudaLaunchKernelEx(&cfg, elem_kernel, L, pE, pA, pI, dirs,
                           (const int2*)conn, E);
    }

    // --- node (PDL: launches while elem drains) ---
    {
        int threads = 256;
        int blocks = (N + threads - 1) / threads;
        if (blocks > 2368) blocks = 2368;
        cudaLaunchConfig_t cfg = {};
        cfg.gridDim  = dim3(blocks);
        cfg.blockDim = dim3(threads);
        cfg.stream   = 0;
        cfg.attrs    = pdl;
        cfg.numAttrs = 1;
        cudaLaunchKernelEx(&cfg, node_kernel, F_ext, bcd, bcr, out, N);
    }
}